// round 13
// baseline (speedup 1.0000x reference)
#include <cuda_runtime.h>
#include <cuda_bf16.h>
#include <math.h>
#include <math_constants.h>

// Problem constants
#define BQ  8
#define HQ  8
#define BH  64          // B*H
#define LQ  2048
#define DQ  64
#define NSEL 40         // num selected queries == num sampled keys
#define SCALE 0.125f    // 64^-0.5
#define NEG_INF (-CUDART_INF_F)

// cumsum chunking: 64 chunks of 32 rows
#define NCHUNK 64
#define CHROWS 32

// key splits: 16 splits of 128 keys (both logits-stats and pv)
#define NJS 16

// packed f32x2 fma (sm_103a): per-lane fp32 FMA, bit-exact vs scalar FFMA
#define FMA_F32X2(acc, a, b) \
    asm("fma.rn.f32x2 %0, %1, %2, %0;" : "+l"(acc) : "l"(a), "l"(b))

// ---------------- scratch (device globals; no allocation allowed) ----------
__device__ float g_measure[BH * LQ];
__device__ int   g_topidx[BH * NSEL];
__device__ float g_rowMaxPart[BH * NJS * NSEL];
__device__ float g_rowSumPart[BH * NJS * NSEL];
__device__ float g_outSelPart[BH * NJS * NSEL * DQ];
__device__ float g_chunkSum[BH * NCHUNK * DQ];

// ============================================================================
// K1: fused  [csumA: 1024 blocks]  +  [measure: 16384 blocks]
// ============================================================================
__global__ __launch_bounds__(256) void k_meas_csumA(const float* __restrict__ q,
                                                    const float* __restrict__ k,
                                                    const int* __restrict__ ridx,
                                                    const float* __restrict__ v) {
    int bid = blockIdx.x;
    if (bid < 1024) {
        // ---- csumA: per-chunk sums. block = (bh, 4 chunks), thread=(sub,d)
        int bh = bid >> 4, cg = bid & 15;
        int t = threadIdx.x;
        int d = t & 63, sub = t >> 6;
        int c = cg * 4 + sub;
        const float* base = v + ((size_t)bh * LQ + c * CHROWS) * DQ;
        float s = 0.0f;
#pragma unroll 8
        for (int r = 0; r < CHROWS; r++) s += base[(size_t)r * DQ + d];
        g_chunkSum[((size_t)bh * NCHUNK + c) * DQ + d] = s;
        return;
    }
    // ---- measure: warp per query; 8 lanes per key
    const unsigned F = 0xffffffffu;
    int warp = ((bid - 1024) * 256 + (int)threadIdx.x) >> 5;
    int lane = threadIdx.x & 31;
    int bh = warp >> 11;
    int i  = warp & 2047;
    int grp = lane >> 3;          // which key of the quad
    int p   = lane & 7;           // float4 slot within 32-dim half

    const float4* qrow = reinterpret_cast<const float4*>(q + ((size_t)bh * LQ + i) * DQ);
    float4 qv0 = qrow[p];
    float4 qv1 = qrow[8 + p];
    const float4* kb4 = reinterpret_cast<const float4*>(k + (size_t)bh * LQ * DQ);
    const int* rbase = ridx + i * NSEL + grp;

    float m = NEG_INF, s = 0.0f;
#pragma unroll
    for (int h = 0; h < NSEL / 4; h += 2) {
        int ra = rbase[4 * h];
        int rb = rbase[4 * h + 4];
        const float4* kra = kb4 + (size_t)ra * (DQ / 4);
        const float4* krb = kb4 + (size_t)rb * (DQ / 4);
        float4 a0 = kra[p];
        float4 a1 = kra[8 + p];
        float4 b0 = krb[p];
        float4 b1 = krb[8 + p];
        float da = qv0.x * a0.x + qv0.y * a0.y + qv0.z * a0.z + qv0.w * a0.w;
        da += qv1.x * a1.x + qv1.y * a1.y + qv1.z * a1.z + qv1.w * a1.w;
        float db = qv0.x * b0.x + qv0.y * b0.y + qv0.z * b0.z + qv0.w * b0.w;
        db += qv1.x * b1.x + qv1.y * b1.y + qv1.z * b1.z + qv1.w * b1.w;
        da += __shfl_xor_sync(F, da, 1);
        db += __shfl_xor_sync(F, db, 1);
        da += __shfl_xor_sync(F, da, 2);
        db += __shfl_xor_sync(F, db, 2);
        da += __shfl_xor_sync(F, da, 4);
        db += __shfl_xor_sync(F, db, 4);
        m = fmaxf(m, fmaxf(da, db));
        s += da + db;
    }
    m = fmaxf(m, __shfl_xor_sync(F, m, 8));
    s += __shfl_xor_sync(F, s, 8);
    m = fmaxf(m, __shfl_xor_sync(F, m, 16));
    s += __shfl_xor_sync(F, s, 16);
    if (lane == 0) g_measure[bh * LQ + i] = m - s * (1.0f / (float)LQ);
}

// ============================================================================
// K2: fused  [topk: 64 blocks]  +  [csumB: 64 blocks]
// ============================================================================
__global__ __launch_bounds__(256) void k_topk_csumB() {
    int bid = blockIdx.x;
    if (bid >= BH) {
        // ---- csumB
        int bh = bid - BH;
        int d = threadIdx.x;
        if (d < DQ) {
            float run = 0.0f;
#pragma unroll
            for (int c = 0; c < NCHUNK; c++) {
                size_t a = ((size_t)bh * NCHUNK + c) * DQ + d;
                float x = g_chunkSum[a];
                g_chunkSum[a] = run;   // exclusive
                run += x;
            }
        }
        return;
    }
    // ---- topk: radix select + rank sort
    __shared__ unsigned ukey[LQ];
    __shared__ int hist[256];
    __shared__ int ssum[256];
    __shared__ int wsum[8];
    __shared__ int s_chosen;
    __shared__ int s_target;
    __shared__ int cnt_gt;
    __shared__ unsigned selKey[64];
    __shared__ int selIdx[64];
    __shared__ int tcnt[256];

    int bh = bid, t = threadIdx.x, lane = t & 31, w = t >> 5;

    for (int e = t; e < LQ; e += 256) {
        unsigned b = __float_as_uint(g_measure[bh * LQ + e]);
        ukey[e] = (b & 0x80000000u) ? ~b : (b | 0x80000000u);
    }
    if (t == 0) { s_target = NSEL; cnt_gt = 0; }
    __syncthreads();

    unsigned prefix = 0;
    for (int pass = 3; pass >= 0; pass--) {
        int shift = pass * 8;
        hist[t] = 0;
        __syncthreads();
        unsigned himask = (pass == 3) ? 0u : (0xFFFFFFFFu << (shift + 8));
        for (int e = t; e < LQ; e += 256) {
            unsigned u = ukey[e];
            if ((u & himask) == (prefix & himask))
                atomicAdd(&hist[(u >> shift) & 255], 1);
        }
        __syncthreads();
        int r = 255 - t;
        int x = hist[r];
#pragma unroll
        for (int o = 1; o < 32; o <<= 1) {
            int y = __shfl_up_sync(0xffffffffu, x, o);
            if (lane >= o) x += y;
        }
        if (lane == 31) wsum[w] = x;
        __syncthreads();
        if (w == 0 && lane < 8) {
            int y = wsum[lane];
#pragma unroll
            for (int o = 1; o < 8; o <<= 1) {
                int z = __shfl_up_sync(0xffu, y, o);
                if (lane >= o) y += z;
            }
            wsum[lane] = y;
        }
        __syncthreads();
        int S = x + (w > 0 ? wsum[w - 1] : 0);
        ssum[r] = S;
        __syncthreads();
        int target = s_target;
        int Sb = ssum[t];
        int Sb1 = (t == 255) ? 0 : ssum[t + 1];
        if (Sb >= target && Sb1 < target) s_chosen = t;
        __syncthreads();
        int chosen = s_chosen;
        prefix |= ((unsigned)chosen) << shift;
        if (t == 0) s_target = target - ((chosen == 255) ? 0 : ssum[chosen + 1]);
        __syncthreads();
    }
    unsigned T = prefix;
    int need_eq = s_target;
    int count_gt = NSEL - need_eq;

    int mytie = 0;
#pragma unroll
    for (int e2 = 0; e2 < 8; e2++) {
        int e = t * 8 + e2;
        unsigned u = ukey[e];
        if (u > T) {
            int p = atomicAdd(&cnt_gt, 1);
            selKey[p] = u; selIdx[p] = e;
        } else if (u == T) mytie++;
    }
    tcnt[t] = mytie;
    __syncthreads();
    {
        int x = tcnt[t];
#pragma unroll
        for (int o = 1; o < 32; o <<= 1) {
            int y = __shfl_up_sync(0xffffffffu, x, o);
            if (lane >= o) x += y;
        }
        if (lane == 31) wsum[w] = x;
        __syncthreads();
        if (w == 0 && lane < 8) {
            int y = wsum[lane];
#pragma unroll
            for (int o = 1; o < 8; o <<= 1) {
                int z = __shfl_up_sync(0xffu, y, o);
                if (lane >= o) y += z;
            }
            wsum[lane] = y;
        }
        __syncthreads();
        int run = x - tcnt[t] + (w > 0 ? wsum[w - 1] : 0);
#pragma unroll
        for (int e2 = 0; e2 < 8; e2++) {
            int e = t * 8 + e2;
            if (ukey[e] == T) {
                if (run < need_eq) { selKey[count_gt + run] = T; selIdx[count_gt + run] = e; }
                run++;
            }
        }
    }
    __syncthreads();
    if (t < NSEL) {
        unsigned mk = selKey[t]; int mi = selIdx[t];
        int rank = 0;
        for (int f = 0; f < NSEL; f++) {
            unsigned fk = selKey[f]; int fi = selIdx[f];
            if (fk > mk || (fk == mk && fi < mi)) rank++;
        }
        g_topidx[bh * NSEL + rank] = mi;
    }
}

// ============================================================================
// K3: logits, 1024 blocks of 128 keys (2 subtiles of 64).
// Thread owns 2 keys (tx, tx+32) x 5 row-groups: 7 LDS / 10 FMA per d-iter.
// smem 27KB. Partial stats per 128-key split (16 per row).
// ============================================================================
__global__ __launch_bounds__(256) void k_logits(const float* __restrict__ q,
                                                const float* __restrict__ k,
                                                float* __restrict__ attn) {
    __shared__ float qs[NSEL * DQ];        // 10.24 KB
    __shared__ float ks[64 * 65];          // 16.64 KB (padded)
    __shared__ int   sidx[NSEL];

    int bh = blockIdx.x >> 4, js = blockIdx.x & 15, t = threadIdx.x;
    if (t < NSEL) sidx[t] = g_topidx[bh * NSEL + t];
    __syncthreads();

    for (int e = t; e < NSEL * DQ; e += 256) {
        int s = e >> 6, d = e & 63;
        qs[e] = q[((size_t)bh * LQ + sidx[s]) * DQ + d];
    }

    float* attnBH = attn + (size_t)bh * NSEL * LQ;
    int tx = t & 31, ty = t >> 5;   // tx: key col (2 keys: tx, tx+32); ty: 8 row groups

    for (int sub = 0; sub < 2; sub++) {
        int j0 = js * 128 + sub * 64;
        __syncthreads();
        for (int e = t; e < 64 * DQ; e += 256) {
            int r = e >> 6, d = e & 63;
            ks[r * 65 + d] = k[((size_t)bh * LQ + j0 + r) * DQ + d];
        }
        __syncthreads();

        float acc[5][2];
#pragma unroll
        for (int r = 0; r < 5; r++) { acc[r][0] = 0.0f; acc[r][1] = 0.0f; }

#pragma unroll 4
        for (int d = 0; d < DQ; d++) {
            float k0 = ks[tx * 65 + d];
            float k1 = ks[(tx + 32) * 65 + d];
#pragma unroll
            for (int r = 0; r < 5; r++) {
                float qv = qs[(ty + 8 * r) * DQ + d];
                acc[r][0] = fmaf(qv, k0, acc[r][0]);
                acc[r][1] = fmaf(qv, k1, acc[r][1]);
            }
        }
#pragma unroll
        for (int r = 0; r < 5; r++) {
            int s = ty + 8 * r;
            int lim = sidx[s];
            int jg0 = j0 + tx;
            int jg1 = j0 + tx + 32;
            attnBH[(size_t)s * LQ + jg0] = (jg0 > lim) ? NEG_INF : acc[r][0] * SCALE;
            attnBH[(size_t)s * LQ + jg1] = (jg1 > lim) ? NEG_INF : acc[r][1] * SCALE;
        }
    }
    __syncthreads();   // make our global logit writes visible block-wide

    // partial softmax stats over this block's 128-key span
    int w = t >> 5, lane = t & 31;
    for (int rr = 0; rr < 5; rr++) {
        int s = w + 8 * rr;
        size_t base = (size_t)s * LQ + js * 128;
        float m = NEG_INF;
#pragma unroll
        for (int u = 0; u < 4; u++) m = fmaxf(m, attnBH[base + lane + 32 * u]);
        m = fmaxf(m, __shfl_xor_sync(0xffffffffu, m, 16));
        m = fmaxf(m, __shfl_xor_sync(0xffffffffu, m, 8));
        m = fmaxf(m, __shfl_xor_sync(0xffffffffu, m, 4));
        m = fmaxf(m, __shfl_xor_sync(0xffffffffu, m, 2));
        m = fmaxf(m, __shfl_xor_sync(0xffffffffu, m, 1));
        float ssum = 0.0f;
        if (m > NEG_INF) {
#pragma unroll
            for (int u = 0; u < 4; u++) ssum += expf(attnBH[base + lane + 32 * u] - m);
        }
        ssum += __shfl_xor_sync(0xffffffffu, ssum, 16);
        ssum += __shfl_xor_sync(0xffffffffu, ssum, 8);
        ssum += __shfl_xor_sync(0xffffffffu, ssum, 4);
        ssum += __shfl_xor_sync(0xffffffffu, ssum, 2);
        ssum += __shfl_xor_sync(0xffffffffu, ssum, 1);
        if (lane == 0) {
            g_rowMaxPart[(bh * NJS + js) * NSEL + s] = m;
            g_rowSumPart[(bh * NJS + js) * NSEL + s] = ssum;
        }
    }
}

// ============================================================================
// K4: fused [csumC: 1024 blocks] + [pv: 1024 blocks].
// launch_bounds(256,6): 6 CTAs/SM (smem 37KB x 6 = 222KB fits 228KB).
// ============================================================================
__global__ __launch_bounds__(256, 6) void k_pv_csumC(const float* __restrict__ v,
                                                     float* __restrict__ attn,
                                                     float* __restrict__ out) {
    __shared__ float vs[64 * DQ];                  // 16 KB
    __shared__ unsigned long long pp[NSEL * 64];   // 20 KB duplicated prob pairs
    __shared__ float sMax[NSEL], sInv[NSEL];

    int bid = blockIdx.x;
    if (bid < 1024) {
        // ---- csumC
        int bh = bid >> 4, cg = bid & 15;
        int t = threadIdx.x;
        int d = t & 63, sub = t >> 6;
        int c = cg * 4 + sub;
        const float* base = v + ((size_t)bh * LQ + c * CHROWS) * DQ;
        float* obase = out + ((size_t)bh * LQ + c * CHROWS) * DQ;
        float run = g_chunkSum[((size_t)bh * NCHUNK + c) * DQ + d];
#pragma unroll 8
        for (int r = 0; r < CHROWS; r++) {
            run += base[(size_t)r * DQ + d];
            obase[(size_t)r * DQ + d] = run;
        }
        return;
    }
    // ---- pv
    int lb = bid - 1024;
    int bh = lb >> 4, js = lb & 15, t = threadIdx.x;
    if (t < NSEL) {
        float fm = NEG_INF;
#pragma unroll
        for (int p = 0; p < NJS; p++)
            fm = fmaxf(fm, g_rowMaxPart[(bh * NJS + p) * NSEL + t]);
        float fs = 0.0f;
#pragma unroll
        for (int p = 0; p < NJS; p++) {
            float pm = g_rowMaxPart[(bh * NJS + p) * NSEL + t];
            float pssum = g_rowSumPart[(bh * NJS + p) * NSEL + t];
            fs += pssum * expf(pm - fm);   // pm=-inf -> pssum==0 -> 0
        }
        sMax[t] = fm;
        sInv[t] = 1.0f / fs;
    }

    float* attnBH = attn + (size_t)bh * NSEL * LQ;
    const float* vBH = v + (size_t)bh * LQ * DQ;

    int tx = t & 31;        // d-pair: d = 2*tx
    int rg = t >> 5;        // row group: rows rg + 8r, r < 5

    unsigned long long acc[5];
#pragma unroll
    for (int r = 0; r < 5; r++) acc[r] = 0ull;
    __syncthreads();

#pragma unroll
    for (int tile = 0; tile < 2; tile++) {
        int j0 = js * 128 + tile * 64;
        __syncthreads();
        // stage V tile (64 x 64)
        const float4* vsrc = reinterpret_cast<const float4*>(vBH + (size_t)j0 * DQ);
        float4* vdst = reinterpret_cast<float4*>(vs);
        for (int e = t; e < 64 * DQ / 4; e += 256) vdst[e] = vsrc[e];
        // probs: read logit, exp-normalize, write back to attn, stage {p,p}
        for (int e = t; e < NSEL * 64; e += 256) {
            int s = e >> 6, jj = e & 63;
            size_t a = (size_t)s * LQ + j0 + jj;
            float l = attnBH[a];
            float p = expf(l - sMax[s]) * sInv[s];
            attnBH[a] = p;
            float2 pr = make_float2(p, p);
            pp[e] = *reinterpret_cast<unsigned long long*>(&pr);
        }
        __syncthreads();
#pragma unroll 4
        for (int jl = 0; jl < 64; jl++) {
            unsigned long long vv =
                *reinterpret_cast<const unsigned long long*>(&vs[jl * DQ + 2 * tx]);
#pragma unroll
            for (int r = 0; r < 5; r++) {
                unsigned long long pr = pp[(rg + 8 * r) * 64 + jl];  // bcast LDS.64
                FMA_F32X2(acc[r], pr, vv);
            }
        }
    }
    // store partial: thread owns rows rg+8r, d-pair 2tx (coalesced float2)
    float* part = g_outSelPart + ((size_t)(bh * NJS + js)) * NSEL * DQ;
#pragma unroll
    for (int r = 0; r < 5; r++) {
        int s = rg + 8 * r;
        *reinterpret_cast<float2*>(&part[s * DQ + 2 * tx]) =
            *reinterpret_cast<float2*>(&acc[r]);
    }
}

// ============================================================================
// K5: sum the NJS P@V partials, scatter into out at the selected positions
// ============================================================================
__global__ void k_scatter(float* __restrict__ out) {   // grid BH, 256 thr
    int bh = blockIdx.x, t = threadIdx.x;
    const float* base = g_outSelPart + (size_t)bh * NJS * NSEL * DQ;
    for (int e = t; e < NSEL * DQ; e += 256) {
        int s = e >> 6, d = e & 63;
        float acc = 0.0f;
#pragma unroll
        for (int p = 0; p < NJS; p++) acc += base[(size_t)p * NSEL * DQ + e];
        out[((size_t)bh * LQ + g_topidx[bh * NSEL + s]) * DQ + d] = acc;
    }
}

// ============================================================================
extern "C" void kernel_launch(void* const* d_in, const int* in_sizes, int n_in,
                              void* d_out, int out_size) {
    const float* q = (const float*)d_in[0];
    const float* k = (const float*)d_in[1];
    const float* v = (const float*)d_in[2];
    const int* ridx = (const int*)d_in[3];

    float* out  = (float*)d_out;                        // [BH, L, D]
    float* attn = out + (size_t)BH * LQ * DQ;           // [BH, NSEL, L]

    // K1: csumA (1024 blocks, first) + measure (16384 blocks)
    k_meas_csumA<<<1024 + (BH * LQ) / 8, 256>>>(q, k, ridx, v);
    // K2: topk (64) + csumB (64)
    k_topk_csumB<<<2 * BH, 256>>>();
    // K3: logits (1024 blocks of 128 keys)
    k_logits<<<BH * NJS, 256>>>(q, k, attn);
    // K4: csumC (1024, first) + pv (1024) — csumC hides under pv
    k_pv_csumC<<<2048, 256>>>(v, attn, out);
    // K5: sum partials + scatter selected rows into out
    k_scatter<<<BH, 256>>>(out);
}

// round 14
// speedup vs baseline: 1.0274x; 1.0274x over previous
#include <cuda_runtime.h>
#include <cuda_bf16.h>
#include <math.h>
#include <math_constants.h>

// Problem constants
#define BQ  8
#define HQ  8
#define BH  64          // B*H
#define LQ  2048
#define DQ  64
#define NSEL 40         // num selected queries == num sampled keys
#define SCALE 0.125f    // 64^-0.5
#define NEG_INF (-CUDART_INF_F)

// cumsum chunking: 64 chunks of 32 rows
#define NCHUNK 64
#define CHROWS 32

// k_pv key splits
#define NJS 16          // 16 splits of 128 keys each

// packed f32x2 fma (sm_103a): per-lane fp32 FMA, bit-exact vs scalar FFMA
#define FMA_F32X2(acc, a, b) \
    asm("fma.rn.f32x2 %0, %1, %2, %0;" : "+l"(acc) : "l"(a), "l"(b))

#define DOT8(q0, q1, a, b) \
    (q0.x * a.x + q0.y * a.y + q0.z * a.z + q0.w * a.w + \
     q1.x * b.x + q1.y * b.y + q1.z * b.z + q1.w * b.w)

// ---------------- scratch (device globals; no allocation allowed) ----------
__device__ float g_measure[BH * LQ];
__device__ int   g_topidx[BH * NSEL];
__device__ float g_rowMaxPart[BH * 8 * NSEL];
__device__ float g_rowSumPart[BH * 8 * NSEL];
__device__ float g_outSelPart[BH * NJS * NSEL * DQ];
__device__ float g_chunkSum[BH * NCHUNK * DQ];

// ============================================================================
// K1: fused  [csumA: 1024 blocks]  +  [measure: 8192 blocks, 2 queries/warp]
// measure: warp handles 2 queries; 8 lanes per key (4 keys per iter per query).
// Per h-iter: 4 independent K-row loads + 2 independent butterfly chains ->
// 2x MLP/ILP per warp at identical per-query instruction count.
// ============================================================================
__global__ __launch_bounds__(256) void k_meas_csumA(const float* __restrict__ q,
                                                    const float* __restrict__ k,
                                                    const int* __restrict__ ridx,
                                                    const float* __restrict__ v) {
    int bid = blockIdx.x;
    if (bid < 1024) {
        // ---- csumA: per-chunk sums. block = (bh, 4 chunks), thread=(sub,d)
        int bh = bid >> 4, cg = bid & 15;
        int t = threadIdx.x;
        int d = t & 63, sub = t >> 6;
        int c = cg * 4 + sub;
        const float* base = v + ((size_t)bh * LQ + c * CHROWS) * DQ;
        float s = 0.0f;
#pragma unroll 8
        for (int r = 0; r < CHROWS; r++) s += base[(size_t)r * DQ + d];
        g_chunkSum[((size_t)bh * NCHUNK + c) * DQ + d] = s;
        return;
    }
    // ---- measure: 2 queries per warp
    const unsigned F = 0xffffffffu;
    int wg = (bid - 1024) * 8 + ((int)threadIdx.x >> 5);
    int lane = threadIdx.x & 31;
    int bh = wg >> 10;
    int i0 = (wg & 1023) * 2;
    int i1 = i0 + 1;
    int grp = lane >> 3;          // which key of the quad
    int p   = lane & 7;           // float4 slot within 32-dim half

    const float4* qrA = reinterpret_cast<const float4*>(q + ((size_t)bh * LQ + i0) * DQ);
    const float4* qrB = reinterpret_cast<const float4*>(q + ((size_t)bh * LQ + i1) * DQ);
    float4 qa0 = qrA[p], qa1 = qrA[8 + p];
    float4 qb0 = qrB[p], qb1 = qrB[8 + p];
    const float4* kb4 = reinterpret_cast<const float4*>(k + (size_t)bh * LQ * DQ);
    const int* riA = ridx + i0 * NSEL + grp;
    const int* riB = ridx + i1 * NSEL + grp;

    float mA = NEG_INF, sA = 0.0f, mB = NEG_INF, sB = 0.0f;
#pragma unroll
    for (int h = 0; h < NSEL / 4; h++) {
        int ra = riA[4 * h];
        int rb = riB[4 * h];
        const float4* kra = kb4 + (size_t)ra * (DQ / 4);
        const float4* krb = kb4 + (size_t)rb * (DQ / 4);
        float4 ka0 = kra[p];
        float4 ka1 = kra[8 + p];
        float4 kc0 = krb[p];
        float4 kc1 = krb[8 + p];
        float da = DOT8(qa0, qa1, ka0, ka1);
        float db = DOT8(qb0, qb1, kc0, kc1);
        da += __shfl_xor_sync(F, da, 1);
        db += __shfl_xor_sync(F, db, 1);
        da += __shfl_xor_sync(F, da, 2);
        db += __shfl_xor_sync(F, db, 2);
        da += __shfl_xor_sync(F, da, 4);
        db += __shfl_xor_sync(F, db, 4);
        mA = fmaxf(mA, da); sA += da;
        mB = fmaxf(mB, db); sB += db;
    }
    // combine across the 4 key-groups (bits 3,4)
    mA = fmaxf(mA, __shfl_xor_sync(F, mA, 8));
    sA += __shfl_xor_sync(F, sA, 8);
    mA = fmaxf(mA, __shfl_xor_sync(F, mA, 16));
    sA += __shfl_xor_sync(F, sA, 16);
    mB = fmaxf(mB, __shfl_xor_sync(F, mB, 8));
    sB += __shfl_xor_sync(F, sB, 8);
    mB = fmaxf(mB, __shfl_xor_sync(F, mB, 16));
    sB += __shfl_xor_sync(F, sB, 16);
    if (lane == 0) {
        g_measure[bh * LQ + i0] = mA - sA * (1.0f / (float)LQ);
        g_measure[bh * LQ + i1] = mB - sB * (1.0f / (float)LQ);
    }
}

// ============================================================================
// K2: fused  [topk: 64 blocks]  +  [csumB: 64 blocks]
// ============================================================================
__global__ __launch_bounds__(256) void k_topk_csumB() {
    int bid = blockIdx.x;
    if (bid >= BH) {
        // ---- csumB
        int bh = bid - BH;
        int d = threadIdx.x;
        if (d < DQ) {
            float run = 0.0f;
#pragma unroll
            for (int c = 0; c < NCHUNK; c++) {
                size_t a = ((size_t)bh * NCHUNK + c) * DQ + d;
                float x = g_chunkSum[a];
                g_chunkSum[a] = run;   // exclusive
                run += x;
            }
        }
        return;
    }
    // ---- topk: radix select + rank sort
    __shared__ unsigned ukey[LQ];
    __shared__ int hist[256];
    __shared__ int ssum[256];
    __shared__ int wsum[8];
    __shared__ int s_chosen;
    __shared__ int s_target;
    __shared__ int cnt_gt;
    __shared__ unsigned selKey[64];
    __shared__ int selIdx[64];
    __shared__ int tcnt[256];

    int bh = bid, t = threadIdx.x, lane = t & 31, w = t >> 5;

    for (int e = t; e < LQ; e += 256) {
        unsigned b = __float_as_uint(g_measure[bh * LQ + e]);
        ukey[e] = (b & 0x80000000u) ? ~b : (b | 0x80000000u);
    }
    if (t == 0) { s_target = NSEL; cnt_gt = 0; }
    __syncthreads();

    unsigned prefix = 0;
    for (int pass = 3; pass >= 0; pass--) {
        int shift = pass * 8;
        hist[t] = 0;
        __syncthreads();
        unsigned himask = (pass == 3) ? 0u : (0xFFFFFFFFu << (shift + 8));
        for (int e = t; e < LQ; e += 256) {
            unsigned u = ukey[e];
            if ((u & himask) == (prefix & himask))
                atomicAdd(&hist[(u >> shift) & 255], 1);
        }
        __syncthreads();
        int r = 255 - t;
        int x = hist[r];
#pragma unroll
        for (int o = 1; o < 32; o <<= 1) {
            int y = __shfl_up_sync(0xffffffffu, x, o);
            if (lane >= o) x += y;
        }
        if (lane == 31) wsum[w] = x;
        __syncthreads();
        if (w == 0 && lane < 8) {
            int y = wsum[lane];
#pragma unroll
            for (int o = 1; o < 8; o <<= 1) {
                int z = __shfl_up_sync(0xffu, y, o);
                if (lane >= o) y += z;
            }
            wsum[lane] = y;
        }
        __syncthreads();
        int S = x + (w > 0 ? wsum[w - 1] : 0);
        ssum[r] = S;
        __syncthreads();
        int target = s_target;
        int Sb = ssum[t];
        int Sb1 = (t == 255) ? 0 : ssum[t + 1];
        if (Sb >= target && Sb1 < target) s_chosen = t;
        __syncthreads();
        int chosen = s_chosen;
        prefix |= ((unsigned)chosen) << shift;
        if (t == 0) s_target = target - ((chosen == 255) ? 0 : ssum[chosen + 1]);
        __syncthreads();
    }
    unsigned T = prefix;
    int need_eq = s_target;
    int count_gt = NSEL - need_eq;

    int mytie = 0;
#pragma unroll
    for (int e2 = 0; e2 < 8; e2++) {
        int e = t * 8 + e2;
        unsigned u = ukey[e];
        if (u > T) {
            int p = atomicAdd(&cnt_gt, 1);
            selKey[p] = u; selIdx[p] = e;
        } else if (u == T) mytie++;
    }
    tcnt[t] = mytie;
    __syncthreads();
    {
        int x = tcnt[t];
#pragma unroll
        for (int o = 1; o < 32; o <<= 1) {
            int y = __shfl_up_sync(0xffffffffu, x, o);
            if (lane >= o) x += y;
        }
        if (lane == 31) wsum[w] = x;
        __syncthreads();
        if (w == 0 && lane < 8) {
            int y = wsum[lane];
#pragma unroll
            for (int o = 1; o < 8; o <<= 1) {
                int z = __shfl_up_sync(0xffu, y, o);
                if (lane >= o) y += z;
            }
            wsum[lane] = y;
        }
        __syncthreads();
        int run = x - tcnt[t] + (w > 0 ? wsum[w - 1] : 0);
#pragma unroll
        for (int e2 = 0; e2 < 8; e2++) {
            int e = t * 8 + e2;
            if (ukey[e] == T) {
                if (run < need_eq) { selKey[count_gt + run] = T; selIdx[count_gt + run] = e; }
                run++;
            }
        }
    }
    __syncthreads();
    if (t < NSEL) {
        unsigned mk = selKey[t]; int mi = selIdx[t];
        int rank = 0;
        for (int f = 0; f < NSEL; f++) {
            unsigned fk = selKey[f]; int fi = selIdx[f];
            if (fk > mk || (fk == mk && fi < mi)) rank++;
        }
        g_topidx[bh * NSEL + rank] = mi;
    }
}

// ============================================================================
// K3: logits only (512 blocks of 256 keys) — R12-proven body.
// ============================================================================
__global__ __launch_bounds__(256) void k_logits(const float* __restrict__ q,
                                                const float* __restrict__ k,
                                                float* __restrict__ attn) {
    __shared__ float qs[NSEL * DQ];        // 40x64
    __shared__ float ks[128 * 65];         // padded
    __shared__ int   sidx[NSEL];

    int bh = blockIdx.x >> 3, js = blockIdx.x & 7, t = threadIdx.x;
    if (t < NSEL) sidx[t] = g_topidx[bh * NSEL + t];
    __syncthreads();

    for (int e = t; e < NSEL * DQ; e += 256) {
        int s = e >> 6, d = e & 63;
        qs[e] = q[((size_t)bh * LQ + sidx[s]) * DQ + d];
    }

    float* attnBH = attn + (size_t)bh * NSEL * LQ;
    int tx = t & 63, ty = t >> 6;

    for (int sub = 0; sub < 2; sub++) {
        int j0 = js * 256 + sub * 128;
        __syncthreads();
        for (int e = t; e < 128 * DQ; e += 256) {
            int r = e >> 6, d = e & 63;
            ks[r * 65 + d] = k[((size_t)bh * LQ + j0 + r) * DQ + d];
        }
        __syncthreads();

        float acc[10][2];
#pragma unroll
        for (int r = 0; r < 10; r++) { acc[r][0] = 0.0f; acc[r][1] = 0.0f; }

#pragma unroll 4
        for (int d = 0; d < DQ; d++) {
            float k0 = ks[tx * 65 + d];
            float k1 = ks[(tx + 64) * 65 + d];
#pragma unroll
            for (int r = 0; r < 10; r++) {
                float qv = qs[(ty + 4 * r) * DQ + d];
                acc[r][0] = fmaf(qv, k0, acc[r][0]);
                acc[r][1] = fmaf(qv, k1, acc[r][1]);
            }
        }
#pragma unroll
        for (int r = 0; r < 10; r++) {
            int s = ty + 4 * r;
            int lim = sidx[s];
            int jg0 = j0 + tx;
            int jg1 = j0 + tx + 64;
            attnBH[(size_t)s * LQ + jg0] = (jg0 > lim) ? NEG_INF : acc[r][0] * SCALE;
            attnBH[(size_t)s * LQ + jg1] = (jg1 > lim) ? NEG_INF : acc[r][1] * SCALE;
        }
    }
    __syncthreads();

    // partial softmax stats over this block's 256-key span
    int w = t >> 5, lane = t & 31;
    for (int rr = 0; rr < 5; rr++) {
        int s = w + 8 * rr;
        size_t base = (size_t)s * LQ + js * 256;
        float m = NEG_INF;
#pragma unroll
        for (int u = 0; u < 8; u++) m = fmaxf(m, attnBH[base + lane + 32 * u]);
        m = fmaxf(m, __shfl_xor_sync(0xffffffffu, m, 16));
        m = fmaxf(m, __shfl_xor_sync(0xffffffffu, m, 8));
        m = fmaxf(m, __shfl_xor_sync(0xffffffffu, m, 4));
        m = fmaxf(m, __shfl_xor_sync(0xffffffffu, m, 2));
        m = fmaxf(m, __shfl_xor_sync(0xffffffffu, m, 1));
        float ssum = 0.0f;
        if (m > NEG_INF) {
#pragma unroll
            for (int u = 0; u < 8; u++) ssum += expf(attnBH[base + lane + 32 * u] - m);
        }
        ssum += __shfl_xor_sync(0xffffffffu, ssum, 16);
        ssum += __shfl_xor_sync(0xffffffffu, ssum, 8);
        ssum += __shfl_xor_sync(0xffffffffu, ssum, 4);
        ssum += __shfl_xor_sync(0xffffffffu, ssum, 2);
        ssum += __shfl_xor_sync(0xffffffffu, ssum, 1);
        if (lane == 0) {
            g_rowMaxPart[(bh * 8 + js) * NSEL + s] = m;
            g_rowSumPart[(bh * 8 + js) * NSEL + s] = ssum;
        }
    }
}

// ============================================================================
// K4: fused [csumC: 1024 blocks] + [pv: 1024 blocks]. (R12-proven)
// launch_bounds(256,5): 48 regs, 5 CTAs/SM.
// ============================================================================
__global__ __launch_bounds__(256, 5) void k_pv_csumC(const float* __restrict__ v,
                                                     float* __restrict__ attn,
                                                     float* __restrict__ out) {
    __shared__ float vs[64 * DQ];                  // 16 KB
    __shared__ unsigned long long pp[NSEL * 64];   // 20 KB duplicated prob pairs
    __shared__ float sMax[NSEL], sInv[NSEL];

    int bid = blockIdx.x;
    if (bid < 1024) {
        // ---- csumC
        int bh = bid >> 4, cg = bid & 15;
        int t = threadIdx.x;
        int d = t & 63, sub = t >> 6;
        int c = cg * 4 + sub;
        const float* base = v + ((size_t)bh * LQ + c * CHROWS) * DQ;
        float* obase = out + ((size_t)bh * LQ + c * CHROWS) * DQ;
        float run = g_chunkSum[((size_t)bh * NCHUNK + c) * DQ + d];
#pragma unroll 8
        for (int r = 0; r < CHROWS; r++) {
            run += base[(size_t)r * DQ + d];
            obase[(size_t)r * DQ + d] = run;
        }
        return;
    }
    // ---- pv
    int lb = bid - 1024;
    int bh = lb >> 4, js = lb & 15, t = threadIdx.x;
    if (t < NSEL) {
        float fm = NEG_INF;
#pragma unroll
        for (int p = 0; p < 8; p++)
            fm = fmaxf(fm, g_rowMaxPart[(bh * 8 + p) * NSEL + t]);
        float fs = 0.0f;
#pragma unroll
        for (int p = 0; p < 8; p++) {
            float pm = g_rowMaxPart[(bh * 8 + p) * NSEL + t];
            float pssum = g_rowSumPart[(bh * 8 + p) * NSEL + t];
            fs += pssum * expf(pm - fm);
        }
        sMax[t] = fm;
        sInv[t] = 1.0f / fs;
    }

    float* attnBH = attn + (size_t)bh * NSEL * LQ;
    const float* vBH = v + (size_t)bh * LQ * DQ;

    int tx = t & 31;        // d-pair: d = 2*tx
    int rg = t >> 5;        // row group: rows rg + 8r, r < 5

    unsigned long long acc[5];
#pragma unroll
    for (int r = 0; r < 5; r++) acc[r] = 0ull;
    __syncthreads();

#pragma unroll
    for (int tile = 0; tile < 2; tile++) {
        int j0 = js * 128 + tile * 64;
        __syncthreads();
        // stage V tile (64 x 64)
        const float4* vsrc = reinterpret_cast<const float4*>(vBH + (size_t)j0 * DQ);
        float4* vdst = reinterpret_cast<float4*>(vs);
        for (int e = t; e < 64 * DQ / 4; e += 256) vdst[e] = vsrc[e];
        // probs: read logit, exp-normalize, write back to attn, stage {p,p}
        for (int e = t; e < NSEL * 64; e += 256) {
            int s = e >> 6, jj = e & 63;
            size_t a = (size_t)s * LQ + j0 + jj;
            float l = attnBH[a];
            float p = expf(l - sMax[s]) * sInv[s];
            attnBH[a] = p;
            float2 pr = make_float2(p, p);
            pp[e] = *reinterpret_cast<unsigned long long*>(&pr);
        }
        __syncthreads();
#pragma unroll 4
        for (int jl = 0; jl < 64; jl++) {
            unsigned long long vv =
                *reinterpret_cast<const unsigned long long*>(&vs[jl * DQ + 2 * tx]);
#pragma unroll
            for (int r = 0; r < 5; r++) {
                unsigned long long pr = pp[(rg + 8 * r) * 64 + jl];  // bcast LDS.64
                FMA_F32X2(acc[r], pr, vv);
            }
        }
    }
    // store partial: thread owns rows rg+8r, d-pair 2tx (coalesced float2)
    float* part = g_outSelPart + ((size_t)(bh * NJS + js)) * NSEL * DQ;
#pragma unroll
    for (int r = 0; r < 5; r++) {
        int s = rg + 8 * r;
        *reinterpret_cast<float2*>(&part[s * DQ + 2 * tx]) =
            *reinterpret_cast<float2*>(&acc[r]);
    }
}

// ============================================================================
// K5: sum the NJS P@V partials, scatter into out at the selected positions
// ============================================================================
__global__ void k_scatter(float* __restrict__ out) {   // grid BH, 256 thr
    int bh = blockIdx.x, t = threadIdx.x;
    const float* base = g_outSelPart + (size_t)bh * NJS * NSEL * DQ;
    for (int e = t; e < NSEL * DQ; e += 256) {
        int s = e >> 6, d = e & 63;
        float acc = 0.0f;
#pragma unroll
        for (int p = 0; p < NJS; p++) acc += base[(size_t)p * NSEL * DQ + e];
        out[((size_t)bh * LQ + g_topidx[bh * NSEL + s]) * DQ + d] = acc;
    }
}

// ============================================================================
extern "C" void kernel_launch(void* const* d_in, const int* in_sizes, int n_in,
                              void* d_out, int out_size) {
    const float* q = (const float*)d_in[0];
    const float* k = (const float*)d_in[1];
    const float* v = (const float*)d_in[2];
    const int* ridx = (const int*)d_in[3];

    float* out  = (float*)d_out;                        // [BH, L, D]
    float* attn = out + (size_t)BH * LQ * DQ;           // [BH, NSEL, L]

    // K1: csumA (1024 blocks, first) + measure (8192 blocks, 2 queries/warp)
    k_meas_csumA<<<1024 + (BH * LQ) / 16, 256>>>(q, k, ridx, v);
    // K2: topk (64) + csumB (64)
    k_topk_csumB<<<2 * BH, 256>>>();
    // K3: logits (512 blocks of 256 keys)
    k_logits<<<BH * 8, 256>>>(q, k, attn);
    // K4: csumC (1024, first) + pv (1024) — csumC hides under pv
    k_pv_csumC<<<2048, 256>>>(v, attn, out);
    // K5: sum partials + scatter selected rows into out
    k_scatter<<<BH, 256>>>(out);
}

// round 15
// speedup vs baseline: 1.0413x; 1.0135x over previous
#include <cuda_runtime.h>
#include <cuda_bf16.h>
#include <math.h>
#include <math_constants.h>

// Problem constants
#define BQ  8
#define HQ  8
#define BH  64          // B*H
#define LQ  2048
#define DQ  64
#define NSEL 40         // num selected queries == num sampled keys
#define SCALE 0.125f    // 64^-0.5
#define NEG_INF (-CUDART_INF_F)

// cumsum chunking: 64 chunks of 32 rows
#define NCHUNK 64
#define CHROWS 32

// pv key splits: 32 splits of 64 keys (single tile per block)
#define NJS 32

// packed f32x2 fma (sm_103a): per-lane fp32 FMA, bit-exact vs scalar FFMA
#define FMA_F32X2(acc, a, b) \
    asm("fma.rn.f32x2 %0, %1, %2, %0;" : "+l"(acc) : "l"(a), "l"(b))

// ---------------- scratch (device globals; no allocation allowed) ----------
__device__ float g_measure[BH * LQ];
__device__ int   g_topidx[BH * NSEL];
__device__ float g_rowMaxPart[BH * 8 * NSEL];
__device__ float g_rowSumPart[BH * 8 * NSEL];
__device__ float g_outSelPart[BH * NJS * NSEL * DQ];
__device__ float g_chunkSum[BH * NCHUNK * DQ];

// ============================================================================
// K1: fused  [csumA: 1024 blocks]  +  [measure: 16384 blocks]  (R12-proven)
// ============================================================================
__global__ __launch_bounds__(256) void k_meas_csumA(const float* __restrict__ q,
                                                    const float* __restrict__ k,
                                                    const int* __restrict__ ridx,
                                                    const float* __restrict__ v) {
    int bid = blockIdx.x;
    if (bid < 1024) {
        // ---- csumA: per-chunk sums. block = (bh, 4 chunks), thread=(sub,d)
        int bh = bid >> 4, cg = bid & 15;
        int t = threadIdx.x;
        int d = t & 63, sub = t >> 6;
        int c = cg * 4 + sub;
        const float* base = v + ((size_t)bh * LQ + c * CHROWS) * DQ;
        float s = 0.0f;
#pragma unroll 8
        for (int r = 0; r < CHROWS; r++) s += base[(size_t)r * DQ + d];
        g_chunkSum[((size_t)bh * NCHUNK + c) * DQ + d] = s;
        return;
    }
    // ---- measure: warp per query; 8 lanes per key
    const unsigned F = 0xffffffffu;
    int warp = ((bid - 1024) * 256 + (int)threadIdx.x) >> 5;
    int lane = threadIdx.x & 31;
    int bh = warp >> 11;
    int i  = warp & 2047;
    int grp = lane >> 3;          // which key of the quad
    int p   = lane & 7;           // float4 slot within 32-dim half

    const float4* qrow = reinterpret_cast<const float4*>(q + ((size_t)bh * LQ + i) * DQ);
    float4 qv0 = qrow[p];
    float4 qv1 = qrow[8 + p];
    const float4* kb4 = reinterpret_cast<const float4*>(k + (size_t)bh * LQ * DQ);
    const int* rbase = ridx + i * NSEL + grp;

    float m = NEG_INF, s = 0.0f;
#pragma unroll
    for (int h = 0; h < NSEL / 4; h += 2) {
        int ra = rbase[4 * h];
        int rb = rbase[4 * h + 4];
        const float4* kra = kb4 + (size_t)ra * (DQ / 4);
        const float4* krb = kb4 + (size_t)rb * (DQ / 4);
        float4 a0 = kra[p];
        float4 a1 = kra[8 + p];
        float4 b0 = krb[p];
        float4 b1 = krb[8 + p];
        float da = qv0.x * a0.x + qv0.y * a0.y + qv0.z * a0.z + qv0.w * a0.w;
        da += qv1.x * a1.x + qv1.y * a1.y + qv1.z * a1.z + qv1.w * a1.w;
        float db = qv0.x * b0.x + qv0.y * b0.y + qv0.z * b0.z + qv0.w * b0.w;
        db += qv1.x * b1.x + qv1.y * b1.y + qv1.z * b1.z + qv1.w * b1.w;
        da += __shfl_xor_sync(F, da, 1);
        db += __shfl_xor_sync(F, db, 1);
        da += __shfl_xor_sync(F, da, 2);
        db += __shfl_xor_sync(F, db, 2);
        da += __shfl_xor_sync(F, da, 4);
        db += __shfl_xor_sync(F, db, 4);
        m = fmaxf(m, fmaxf(da, db));
        s += da + db;
    }
    m = fmaxf(m, __shfl_xor_sync(F, m, 8));
    s += __shfl_xor_sync(F, s, 8);
    m = fmaxf(m, __shfl_xor_sync(F, m, 16));
    s += __shfl_xor_sync(F, s, 16);
    if (lane == 0) g_measure[bh * LQ + i] = m - s * (1.0f / (float)LQ);
}

// ============================================================================
// K2: fused  [topk: 64 blocks]  +  [csumB: 64 blocks]
// ============================================================================
__global__ __launch_bounds__(256) void k_topk_csumB() {
    int bid = blockIdx.x;
    if (bid >= BH) {
        // ---- csumB
        int bh = bid - BH;
        int d = threadIdx.x;
        if (d < DQ) {
            float run = 0.0f;
#pragma unroll
            for (int c = 0; c < NCHUNK; c++) {
                size_t a = ((size_t)bh * NCHUNK + c) * DQ + d;
                float x = g_chunkSum[a];
                g_chunkSum[a] = run;   // exclusive
                run += x;
            }
        }
        return;
    }
    // ---- topk: radix select + rank sort
    __shared__ unsigned ukey[LQ];
    __shared__ int hist[256];
    __shared__ int ssum[256];
    __shared__ int wsum[8];
    __shared__ int s_chosen;
    __shared__ int s_target;
    __shared__ int cnt_gt;
    __shared__ unsigned selKey[64];
    __shared__ int selIdx[64];
    __shared__ int tcnt[256];

    int bh = bid, t = threadIdx.x, lane = t & 31, w = t >> 5;

    for (int e = t; e < LQ; e += 256) {
        unsigned b = __float_as_uint(g_measure[bh * LQ + e]);
        ukey[e] = (b & 0x80000000u) ? ~b : (b | 0x80000000u);
    }
    if (t == 0) { s_target = NSEL; cnt_gt = 0; }
    __syncthreads();

    unsigned prefix = 0;
    for (int pass = 3; pass >= 0; pass--) {
        int shift = pass * 8;
        hist[t] = 0;
        __syncthreads();
        unsigned himask = (pass == 3) ? 0u : (0xFFFFFFFFu << (shift + 8));
        for (int e = t; e < LQ; e += 256) {
            unsigned u = ukey[e];
            if ((u & himask) == (prefix & himask))
                atomicAdd(&hist[(u >> shift) & 255], 1);
        }
        __syncthreads();
        int r = 255 - t;
        int x = hist[r];
#pragma unroll
        for (int o = 1; o < 32; o <<= 1) {
            int y = __shfl_up_sync(0xffffffffu, x, o);
            if (lane >= o) x += y;
        }
        if (lane == 31) wsum[w] = x;
        __syncthreads();
        if (w == 0 && lane < 8) {
            int y = wsum[lane];
#pragma unroll
            for (int o = 1; o < 8; o <<= 1) {
                int z = __shfl_up_sync(0xffu, y, o);
                if (lane >= o) y += z;
            }
            wsum[lane] = y;
        }
        __syncthreads();
        int S = x + (w > 0 ? wsum[w - 1] : 0);
        ssum[r] = S;
        __syncthreads();
        int target = s_target;
        int Sb = ssum[t];
        int Sb1 = (t == 255) ? 0 : ssum[t + 1];
        if (Sb >= target && Sb1 < target) s_chosen = t;
        __syncthreads();
        int chosen = s_chosen;
        prefix |= ((unsigned)chosen) << shift;
        if (t == 0) s_target = target - ((chosen == 255) ? 0 : ssum[chosen + 1]);
        __syncthreads();
    }
    unsigned T = prefix;
    int need_eq = s_target;
    int count_gt = NSEL - need_eq;

    int mytie = 0;
#pragma unroll
    for (int e2 = 0; e2 < 8; e2++) {
        int e = t * 8 + e2;
        unsigned u = ukey[e];
        if (u > T) {
            int p = atomicAdd(&cnt_gt, 1);
            selKey[p] = u; selIdx[p] = e;
        } else if (u == T) mytie++;
    }
    tcnt[t] = mytie;
    __syncthreads();
    {
        int x = tcnt[t];
#pragma unroll
        for (int o = 1; o < 32; o <<= 1) {
            int y = __shfl_up_sync(0xffffffffu, x, o);
            if (lane >= o) x += y;
        }
        if (lane == 31) wsum[w] = x;
        __syncthreads();
        if (w == 0 && lane < 8) {
            int y = wsum[lane];
#pragma unroll
            for (int o = 1; o < 8; o <<= 1) {
                int z = __shfl_up_sync(0xffu, y, o);
                if (lane >= o) y += z;
            }
            wsum[lane] = y;
        }
        __syncthreads();
        int run = x - tcnt[t] + (w > 0 ? wsum[w - 1] : 0);
#pragma unroll
        for (int e2 = 0; e2 < 8; e2++) {
            int e = t * 8 + e2;
            if (ukey[e] == T) {
                if (run < need_eq) { selKey[count_gt + run] = T; selIdx[count_gt + run] = e; }
                run++;
            }
        }
    }
    __syncthreads();
    if (t < NSEL) {
        unsigned mk = selKey[t]; int mi = selIdx[t];
        int rank = 0;
        for (int f = 0; f < NSEL; f++) {
            unsigned fk = selKey[f]; int fi = selIdx[f];
            if (fk > mk || (fk == mk && fi < mi)) rank++;
        }
        g_topidx[bh * NSEL + rank] = mi;
    }
}

// ============================================================================
// K3: logits only (512 blocks of 256 keys) — R12-proven body.
// ============================================================================
__global__ __launch_bounds__(256) void k_logits(const float* __restrict__ q,
                                                const float* __restrict__ k,
                                                float* __restrict__ attn) {
    __shared__ float qs[NSEL * DQ];        // 40x64
    __shared__ float ks[128 * 65];         // padded
    __shared__ int   sidx[NSEL];

    int bh = blockIdx.x >> 3, js = blockIdx.x & 7, t = threadIdx.x;
    if (t < NSEL) sidx[t] = g_topidx[bh * NSEL + t];
    __syncthreads();

    for (int e = t; e < NSEL * DQ; e += 256) {
        int s = e >> 6, d = e & 63;
        qs[e] = q[((size_t)bh * LQ + sidx[s]) * DQ + d];
    }

    float* attnBH = attn + (size_t)bh * NSEL * LQ;
    int tx = t & 63, ty = t >> 6;

    for (int sub = 0; sub < 2; sub++) {
        int j0 = js * 256 + sub * 128;
        __syncthreads();
        for (int e = t; e < 128 * DQ; e += 256) {
            int r = e >> 6, d = e & 63;
            ks[r * 65 + d] = k[((size_t)bh * LQ + j0 + r) * DQ + d];
        }
        __syncthreads();

        float acc[10][2];
#pragma unroll
        for (int r = 0; r < 10; r++) { acc[r][0] = 0.0f; acc[r][1] = 0.0f; }

#pragma unroll 4
        for (int d = 0; d < DQ; d++) {
            float k0 = ks[tx * 65 + d];
            float k1 = ks[(tx + 64) * 65 + d];
#pragma unroll
            for (int r = 0; r < 10; r++) {
                float qv = qs[(ty + 4 * r) * DQ + d];
                acc[r][0] = fmaf(qv, k0, acc[r][0]);
                acc[r][1] = fmaf(qv, k1, acc[r][1]);
            }
        }
#pragma unroll
        for (int r = 0; r < 10; r++) {
            int s = ty + 4 * r;
            int lim = sidx[s];
            int jg0 = j0 + tx;
            int jg1 = j0 + tx + 64;
            attnBH[(size_t)s * LQ + jg0] = (jg0 > lim) ? NEG_INF : acc[r][0] * SCALE;
            attnBH[(size_t)s * LQ + jg1] = (jg1 > lim) ? NEG_INF : acc[r][1] * SCALE;
        }
    }
    __syncthreads();

    // partial softmax stats over this block's 256-key span
    int w = t >> 5, lane = t & 31;
    for (int rr = 0; rr < 5; rr++) {
        int s = w + 8 * rr;
        size_t base = (size_t)s * LQ + js * 256;
        float m = NEG_INF;
#pragma unroll
        for (int u = 0; u < 8; u++) m = fmaxf(m, attnBH[base + lane + 32 * u]);
        m = fmaxf(m, __shfl_xor_sync(0xffffffffu, m, 16));
        m = fmaxf(m, __shfl_xor_sync(0xffffffffu, m, 8));
        m = fmaxf(m, __shfl_xor_sync(0xffffffffu, m, 4));
        m = fmaxf(m, __shfl_xor_sync(0xffffffffu, m, 2));
        m = fmaxf(m, __shfl_xor_sync(0xffffffffu, m, 1));
        float ssum = 0.0f;
        if (m > NEG_INF) {
#pragma unroll
            for (int u = 0; u < 8; u++) ssum += expf(attnBH[base + lane + 32 * u] - m);
        }
        ssum += __shfl_xor_sync(0xffffffffu, ssum, 16);
        ssum += __shfl_xor_sync(0xffffffffu, ssum, 8);
        ssum += __shfl_xor_sync(0xffffffffu, ssum, 4);
        ssum += __shfl_xor_sync(0xffffffffu, ssum, 2);
        ssum += __shfl_xor_sync(0xffffffffu, ssum, 1);
        if (lane == 0) {
            g_rowMaxPart[(bh * 8 + js) * NSEL + s] = m;
            g_rowSumPart[(bh * 8 + js) * NSEL + s] = ssum;
        }
    }
}

// ============================================================================
// K4: fused [csumC: 1024 blocks] + [pv: 2048 blocks of 64 keys, single tile].
// Single tile -> half the sync-separated phases per block; 2x block count
// (block-count scaling is the lever that moved pv before).
// ============================================================================
__global__ __launch_bounds__(256, 5) void k_pv_csumC(const float* __restrict__ v,
                                                     float* __restrict__ attn,
                                                     float* __restrict__ out) {
    __shared__ float vs[64 * DQ];                  // 16 KB
    __shared__ unsigned long long pp[NSEL * 64];   // 20 KB duplicated prob pairs
    __shared__ float sMax[NSEL], sInv[NSEL];

    int bid = blockIdx.x;
    if (bid < 1024) {
        // ---- csumC
        int bh = bid >> 4, cg = bid & 15;
        int t = threadIdx.x;
        int d = t & 63, sub = t >> 6;
        int c = cg * 4 + sub;
        const float* base = v + ((size_t)bh * LQ + c * CHROWS) * DQ;
        float* obase = out + ((size_t)bh * LQ + c * CHROWS) * DQ;
        float run = g_chunkSum[((size_t)bh * NCHUNK + c) * DQ + d];
#pragma unroll 8
        for (int r = 0; r < CHROWS; r++) {
            run += base[(size_t)r * DQ + d];
            obase[(size_t)r * DQ + d] = run;
        }
        return;
    }
    // ---- pv: single 64-key tile
    int lb = bid - 1024;
    int bh = lb >> 5, js = lb & 31, t = threadIdx.x;
    if (t < NSEL) {
        float fm = NEG_INF;
#pragma unroll
        for (int p = 0; p < 8; p++)
            fm = fmaxf(fm, g_rowMaxPart[(bh * 8 + p) * NSEL + t]);
        float fs = 0.0f;
#pragma unroll
        for (int p = 0; p < 8; p++) {
            float pm = g_rowMaxPart[(bh * 8 + p) * NSEL + t];
            float pssum = g_rowSumPart[(bh * 8 + p) * NSEL + t];
            fs += pssum * expf(pm - fm);
        }
        sMax[t] = fm;
        sInv[t] = 1.0f / fs;
    }

    float* attnBH = attn + (size_t)bh * NSEL * LQ;
    const float* vBH = v + (size_t)bh * LQ * DQ;

    int tx = t & 31;        // d-pair: d = 2*tx
    int rg = t >> 5;        // row group: rows rg + 8r, r < 5
    int j0 = js * 64;

    // stage V tile (64 x 64) — no dependence on sMax/sInv
    {
        const float4* vsrc = reinterpret_cast<const float4*>(vBH + (size_t)j0 * DQ);
        float4* vdst = reinterpret_cast<float4*>(vs);
        for (int e = t; e < 64 * DQ / 4; e += 256) vdst[e] = vsrc[e];
    }
    __syncthreads();   // sMax/sInv ready (also covers vs/pp writes below)

    // probs: read logit, exp-normalize, write back to attn, stage {p,p}
    for (int e = t; e < NSEL * 64; e += 256) {
        int s = e >> 6, jj = e & 63;
        size_t a = (size_t)s * LQ + j0 + jj;
        float l = attnBH[a];
        float p = expf(l - sMax[s]) * sInv[s];
        attnBH[a] = p;
        float2 pr = make_float2(p, p);
        pp[e] = *reinterpret_cast<unsigned long long*>(&pr);
    }
    __syncthreads();

    unsigned long long acc[5];
#pragma unroll
    for (int r = 0; r < 5; r++) acc[r] = 0ull;
#pragma unroll 4
    for (int jl = 0; jl < 64; jl++) {
        unsigned long long vv =
            *reinterpret_cast<const unsigned long long*>(&vs[jl * DQ + 2 * tx]);
#pragma unroll
        for (int r = 0; r < 5; r++) {
            unsigned long long pr = pp[(rg + 8 * r) * 64 + jl];  // bcast LDS.64
            FMA_F32X2(acc[r], pr, vv);
        }
    }
    // store partial: thread owns rows rg+8r, d-pair 2tx (coalesced float2)
    float* part = g_outSelPart + ((size_t)(bh * NJS + js)) * NSEL * DQ;
#pragma unroll
    for (int r = 0; r < 5; r++) {
        int s = rg + 8 * r;
        *reinterpret_cast<float2*>(&part[s * DQ + 2 * tx]) =
            *reinterpret_cast<float2*>(&acc[r]);
    }
}

// ============================================================================
// K5: sum the NJS P@V partials, scatter into out at the selected positions
// ============================================================================
__global__ void k_scatter(float* __restrict__ out) {   // grid BH, 256 thr
    int bh = blockIdx.x, t = threadIdx.x;
    const float* base = g_outSelPart + (size_t)bh * NJS * NSEL * DQ;
    for (int e = t; e < NSEL * DQ; e += 256) {
        int s = e >> 6, d = e & 63;
        float acc = 0.0f;
#pragma unroll
        for (int p = 0; p < NJS; p++) acc += base[(size_t)p * NSEL * DQ + e];
        out[((size_t)bh * LQ + g_topidx[bh * NSEL + s]) * DQ + d] = acc;
    }
}

// ============================================================================
extern "C" void kernel_launch(void* const* d_in, const int* in_sizes, int n_in,
                              void* d_out, int out_size) {
    const float* q = (const float*)d_in[0];
    const float* k = (const float*)d_in[1];
    const float* v = (const float*)d_in[2];
    const int* ridx = (const int*)d_in[3];

    float* out  = (float*)d_out;                        // [BH, L, D]
    float* attn = out + (size_t)BH * LQ * DQ;           // [BH, NSEL, L]

    // K1: csumA (1024 blocks, first) + measure (16384 blocks)
    k_meas_csumA<<<1024 + (BH * LQ) / 8, 256>>>(q, k, ridx, v);
    // K2: topk (64) + csumB (64)
    k_topk_csumB<<<2 * BH, 256>>>();
    // K3: logits (512 blocks of 256 keys)
    k_logits<<<BH * 8, 256>>>(q, k, attn);
    // K4: csumC (1024, first) + pv (2048 single-tile blocks)
    k_pv_csumC<<<1024 + BH * NJS, 256>>>(v, attn, out);
    // K5: sum partials + scatter selected rows into out
    k_scatter<<<BH, 256>>>(out);
}

// round 16
// speedup vs baseline: 1.0419x; 1.0005x over previous
#include <cuda_runtime.h>
#include <cuda_bf16.h>
#include <math.h>
#include <math_constants.h>

// Problem constants
#define BQ  8
#define HQ  8
#define BH  64          // B*H
#define LQ  2048
#define DQ  64
#define NSEL 40         // num selected queries == num sampled keys
#define SCALE 0.125f    // 64^-0.5
#define NEG_INF (-CUDART_INF_F)

// cumsum chunking: 64 chunks of 32 rows
#define NCHUNK 64
#define CHROWS 32

// pv key splits: 64 splits of 32 keys (single tile per block)
#define NJS 64
#define TILE 32

// packed f32x2 fma (sm_103a): per-lane fp32 FMA, bit-exact vs scalar FFMA
#define FMA_F32X2(acc, a, b) \
    asm("fma.rn.f32x2 %0, %1, %2, %0;" : "+l"(acc) : "l"(a), "l"(b))

// ---------------- scratch (device globals; no allocation allowed) ----------
__device__ float g_measure[BH * LQ];
__device__ int   g_topidx[BH * NSEL];
__device__ float g_rowMaxPart[BH * 8 * NSEL];
__device__ float g_rowSumPart[BH * 8 * NSEL];
__device__ float g_outSelPart[BH * NJS * NSEL * DQ];   // 42 MB
__device__ float g_chunkSum[BH * NCHUNK * DQ];

// ============================================================================
// K1: fused  [csumA: 1024 blocks]  +  [measure: 16384 blocks]  (proven)
// ============================================================================
__global__ __launch_bounds__(256) void k_meas_csumA(const float* __restrict__ q,
                                                    const float* __restrict__ k,
                                                    const int* __restrict__ ridx,
                                                    const float* __restrict__ v) {
    int bid = blockIdx.x;
    if (bid < 1024) {
        // ---- csumA: per-chunk sums. block = (bh, 4 chunks), thread=(sub,d)
        int bh = bid >> 4, cg = bid & 15;
        int t = threadIdx.x;
        int d = t & 63, sub = t >> 6;
        int c = cg * 4 + sub;
        const float* base = v + ((size_t)bh * LQ + c * CHROWS) * DQ;
        float s = 0.0f;
#pragma unroll 8
        for (int r = 0; r < CHROWS; r++) s += base[(size_t)r * DQ + d];
        g_chunkSum[((size_t)bh * NCHUNK + c) * DQ + d] = s;
        return;
    }
    // ---- measure: warp per query; 8 lanes per key
    const unsigned F = 0xffffffffu;
    int warp = ((bid - 1024) * 256 + (int)threadIdx.x) >> 5;
    int lane = threadIdx.x & 31;
    int bh = warp >> 11;
    int i  = warp & 2047;
    int grp = lane >> 3;          // which key of the quad
    int p   = lane & 7;           // float4 slot within 32-dim half

    const float4* qrow = reinterpret_cast<const float4*>(q + ((size_t)bh * LQ + i) * DQ);
    float4 qv0 = qrow[p];
    float4 qv1 = qrow[8 + p];
    const float4* kb4 = reinterpret_cast<const float4*>(k + (size_t)bh * LQ * DQ);
    const int* rbase = ridx + i * NSEL + grp;

    float m = NEG_INF, s = 0.0f;
#pragma unroll
    for (int h = 0; h < NSEL / 4; h += 2) {
        int ra = rbase[4 * h];
        int rb = rbase[4 * h + 4];
        const float4* kra = kb4 + (size_t)ra * (DQ / 4);
        const float4* krb = kb4 + (size_t)rb * (DQ / 4);
        float4 a0 = kra[p];
        float4 a1 = kra[8 + p];
        float4 b0 = krb[p];
        float4 b1 = krb[8 + p];
        float da = qv0.x * a0.x + qv0.y * a0.y + qv0.z * a0.z + qv0.w * a0.w;
        da += qv1.x * a1.x + qv1.y * a1.y + qv1.z * a1.z + qv1.w * a1.w;
        float db = qv0.x * b0.x + qv0.y * b0.y + qv0.z * b0.z + qv0.w * b0.w;
        db += qv1.x * b1.x + qv1.y * b1.y + qv1.z * b1.z + qv1.w * b1.w;
        da += __shfl_xor_sync(F, da, 1);
        db += __shfl_xor_sync(F, db, 1);
        da += __shfl_xor_sync(F, da, 2);
        db += __shfl_xor_sync(F, db, 2);
        da += __shfl_xor_sync(F, da, 4);
        db += __shfl_xor_sync(F, db, 4);
        m = fmaxf(m, fmaxf(da, db));
        s += da + db;
    }
    m = fmaxf(m, __shfl_xor_sync(F, m, 8));
    s += __shfl_xor_sync(F, s, 8);
    m = fmaxf(m, __shfl_xor_sync(F, m, 16));
    s += __shfl_xor_sync(F, s, 16);
    if (lane == 0) g_measure[bh * LQ + i] = m - s * (1.0f / (float)LQ);
}

// ============================================================================
// K2: fused  [topk: 64 blocks]  +  [csumB: 64 blocks]
// ============================================================================
__global__ __launch_bounds__(256) void k_topk_csumB() {
    int bid = blockIdx.x;
    if (bid >= BH) {
        // ---- csumB
        int bh = bid - BH;
        int d = threadIdx.x;
        if (d < DQ) {
            float run = 0.0f;
#pragma unroll
            for (int c = 0; c < NCHUNK; c++) {
                size_t a = ((size_t)bh * NCHUNK + c) * DQ + d;
                float x = g_chunkSum[a];
                g_chunkSum[a] = run;   // exclusive
                run += x;
            }
        }
        return;
    }
    // ---- topk: radix select + rank sort
    __shared__ unsigned ukey[LQ];
    __shared__ int hist[256];
    __shared__ int ssum[256];
    __shared__ int wsum[8];
    __shared__ int s_chosen;
    __shared__ int s_target;
    __shared__ int cnt_gt;
    __shared__ unsigned selKey[64];
    __shared__ int selIdx[64];
    __shared__ int tcnt[256];

    int bh = bid, t = threadIdx.x, lane = t & 31, w = t >> 5;

    for (int e = t; e < LQ; e += 256) {
        unsigned b = __float_as_uint(g_measure[bh * LQ + e]);
        ukey[e] = (b & 0x80000000u) ? ~b : (b | 0x80000000u);
    }
    if (t == 0) { s_target = NSEL; cnt_gt = 0; }
    __syncthreads();

    unsigned prefix = 0;
    for (int pass = 3; pass >= 0; pass--) {
        int shift = pass * 8;
        hist[t] = 0;
        __syncthreads();
        unsigned himask = (pass == 3) ? 0u : (0xFFFFFFFFu << (shift + 8));
        for (int e = t; e < LQ; e += 256) {
            unsigned u = ukey[e];
            if ((u & himask) == (prefix & himask))
                atomicAdd(&hist[(u >> shift) & 255], 1);
        }
        __syncthreads();
        int r = 255 - t;
        int x = hist[r];
#pragma unroll
        for (int o = 1; o < 32; o <<= 1) {
            int y = __shfl_up_sync(0xffffffffu, x, o);
            if (lane >= o) x += y;
        }
        if (lane == 31) wsum[w] = x;
        __syncthreads();
        if (w == 0 && lane < 8) {
            int y = wsum[lane];
#pragma unroll
            for (int o = 1; o < 8; o <<= 1) {
                int z = __shfl_up_sync(0xffu, y, o);
                if (lane >= o) y += z;
            }
            wsum[lane] = y;
        }
        __syncthreads();
        int S = x + (w > 0 ? wsum[w - 1] : 0);
        ssum[r] = S;
        __syncthreads();
        int target = s_target;
        int Sb = ssum[t];
        int Sb1 = (t == 255) ? 0 : ssum[t + 1];
        if (Sb >= target && Sb1 < target) s_chosen = t;
        __syncthreads();
        int chosen = s_chosen;
        prefix |= ((unsigned)chosen) << shift;
        if (t == 0) s_target = target - ((chosen == 255) ? 0 : ssum[chosen + 1]);
        __syncthreads();
    }
    unsigned T = prefix;
    int need_eq = s_target;
    int count_gt = NSEL - need_eq;

    int mytie = 0;
#pragma unroll
    for (int e2 = 0; e2 < 8; e2++) {
        int e = t * 8 + e2;
        unsigned u = ukey[e];
        if (u > T) {
            int p = atomicAdd(&cnt_gt, 1);
            selKey[p] = u; selIdx[p] = e;
        } else if (u == T) mytie++;
    }
    tcnt[t] = mytie;
    __syncthreads();
    {
        int x = tcnt[t];
#pragma unroll
        for (int o = 1; o < 32; o <<= 1) {
            int y = __shfl_up_sync(0xffffffffu, x, o);
            if (lane >= o) x += y;
        }
        if (lane == 31) wsum[w] = x;
        __syncthreads();
        if (w == 0 && lane < 8) {
            int y = wsum[lane];
#pragma unroll
            for (int o = 1; o < 8; o <<= 1) {
                int z = __shfl_up_sync(0xffu, y, o);
                if (lane >= o) y += z;
            }
            wsum[lane] = y;
        }
        __syncthreads();
        int run = x - tcnt[t] + (w > 0 ? wsum[w - 1] : 0);
#pragma unroll
        for (int e2 = 0; e2 < 8; e2++) {
            int e = t * 8 + e2;
            if (ukey[e] == T) {
                if (run < need_eq) { selKey[count_gt + run] = T; selIdx[count_gt + run] = e; }
                run++;
            }
        }
    }
    __syncthreads();
    if (t < NSEL) {
        unsigned mk = selKey[t]; int mi = selIdx[t];
        int rank = 0;
        for (int f = 0; f < NSEL; f++) {
            unsigned fk = selKey[f]; int fi = selIdx[f];
            if (fk > mk || (fk == mk && fi < mi)) rank++;
        }
        g_topidx[bh * NSEL + rank] = mi;
    }
}

// ============================================================================
// K3: logits only (512 blocks of 256 keys) — proven body.
// ============================================================================
__global__ __launch_bounds__(256) void k_logits(const float* __restrict__ q,
                                                const float* __restrict__ k,
                                                float* __restrict__ attn) {
    __shared__ float qs[NSEL * DQ];        // 40x64
    __shared__ float ks[128 * 65];         // padded
    __shared__ int   sidx[NSEL];

    int bh = blockIdx.x >> 3, js = blockIdx.x & 7, t = threadIdx.x;
    if (t < NSEL) sidx[t] = g_topidx[bh * NSEL + t];
    __syncthreads();

    for (int e = t; e < NSEL * DQ; e += 256) {
        int s = e >> 6, d = e & 63;
        qs[e] = q[((size_t)bh * LQ + sidx[s]) * DQ + d];
    }

    float* attnBH = attn + (size_t)bh * NSEL * LQ;
    int tx = t & 63, ty = t >> 6;

    for (int sub = 0; sub < 2; sub++) {
        int j0 = js * 256 + sub * 128;
        __syncthreads();
        for (int e = t; e < 128 * DQ; e += 256) {
            int r = e >> 6, d = e & 63;
            ks[r * 65 + d] = k[((size_t)bh * LQ + j0 + r) * DQ + d];
        }
        __syncthreads();

        float acc[10][2];
#pragma unroll
        for (int r = 0; r < 10; r++) { acc[r][0] = 0.0f; acc[r][1] = 0.0f; }

#pragma unroll 4
        for (int d = 0; d < DQ; d++) {
            float k0 = ks[tx * 65 + d];
            float k1 = ks[(tx + 64) * 65 + d];
#pragma unroll
            for (int r = 0; r < 10; r++) {
                float qv = qs[(ty + 4 * r) * DQ + d];
                acc[r][0] = fmaf(qv, k0, acc[r][0]);
                acc[r][1] = fmaf(qv, k1, acc[r][1]);
            }
        }
#pragma unroll
        for (int r = 0; r < 10; r++) {
            int s = ty + 4 * r;
            int lim = sidx[s];
            int jg0 = j0 + tx;
            int jg1 = j0 + tx + 64;
            attnBH[(size_t)s * LQ + jg0] = (jg0 > lim) ? NEG_INF : acc[r][0] * SCALE;
            attnBH[(size_t)s * LQ + jg1] = (jg1 > lim) ? NEG_INF : acc[r][1] * SCALE;
        }
    }
    __syncthreads();

    // partial softmax stats over this block's 256-key span
    int w = t >> 5, lane = t & 31;
    for (int rr = 0; rr < 5; rr++) {
        int s = w + 8 * rr;
        size_t base = (size_t)s * LQ + js * 256;
        float m = NEG_INF;
#pragma unroll
        for (int u = 0; u < 8; u++) m = fmaxf(m, attnBH[base + lane + 32 * u]);
        m = fmaxf(m, __shfl_xor_sync(0xffffffffu, m, 16));
        m = fmaxf(m, __shfl_xor_sync(0xffffffffu, m, 8));
        m = fmaxf(m, __shfl_xor_sync(0xffffffffu, m, 4));
        m = fmaxf(m, __shfl_xor_sync(0xffffffffu, m, 2));
        m = fmaxf(m, __shfl_xor_sync(0xffffffffu, m, 1));
        float ssum = 0.0f;
        if (m > NEG_INF) {
#pragma unroll
            for (int u = 0; u < 8; u++) ssum += expf(attnBH[base + lane + 32 * u] - m);
        }
        ssum += __shfl_xor_sync(0xffffffffu, ssum, 16);
        ssum += __shfl_xor_sync(0xffffffffu, ssum, 8);
        ssum += __shfl_xor_sync(0xffffffffu, ssum, 4);
        ssum += __shfl_xor_sync(0xffffffffu, ssum, 2);
        ssum += __shfl_xor_sync(0xffffffffu, ssum, 1);
        if (lane == 0) {
            g_rowMaxPart[(bh * 8 + js) * NSEL + s] = m;
            g_rowSumPart[(bh * 8 + js) * NSEL + s] = ssum;
        }
    }
}

// ============================================================================
// K4: fused [csumC: 1024 blocks] + [pv: 4096 blocks of 32 keys, single tile].
// Block-count scaling continues: per-block critical path halves again.
// ============================================================================
__global__ __launch_bounds__(256, 5) void k_pv_csumC(const float* __restrict__ v,
                                                     float* __restrict__ attn,
                                                     float* __restrict__ out) {
    __shared__ float vs[TILE * DQ];                   // 8 KB
    __shared__ unsigned long long pp[NSEL * TILE];    // 10 KB duplicated prob pairs
    __shared__ float sMax[NSEL], sInv[NSEL];

    int bid = blockIdx.x;
    if (bid < 1024) {
        // ---- csumC
        int bh = bid >> 4, cg = bid & 15;
        int t = threadIdx.x;
        int d = t & 63, sub = t >> 6;
        int c = cg * 4 + sub;
        const float* base = v + ((size_t)bh * LQ + c * CHROWS) * DQ;
        float* obase = out + ((size_t)bh * LQ + c * CHROWS) * DQ;
        float run = g_chunkSum[((size_t)bh * NCHUNK + c) * DQ + d];
#pragma unroll 8
        for (int r = 0; r < CHROWS; r++) {
            run += base[(size_t)r * DQ + d];
            obase[(size_t)r * DQ + d] = run;
        }
        return;
    }
    // ---- pv: single 32-key tile
    int lb = bid - 1024;
    int bh = lb >> 6, js = lb & 63, t = threadIdx.x;
    if (t < NSEL) {
        float fm = NEG_INF;
#pragma unroll
        for (int p = 0; p < 8; p++)
            fm = fmaxf(fm, g_rowMaxPart[(bh * 8 + p) * NSEL + t]);
        float fs = 0.0f;
#pragma unroll
        for (int p = 0; p < 8; p++) {
            float pm = g_rowMaxPart[(bh * 8 + p) * NSEL + t];
            float pssum = g_rowSumPart[(bh * 8 + p) * NSEL + t];
            fs += pssum * expf(pm - fm);
        }
        sMax[t] = fm;
        sInv[t] = 1.0f / fs;
    }

    float* attnBH = attn + (size_t)bh * NSEL * LQ;
    const float* vBH = v + (size_t)bh * LQ * DQ;

    int tx = t & 31;        // d-pair: d = 2*tx
    int rg = t >> 5;        // row group: rows rg + 8r, r < 5
    int j0 = js * TILE;

    // stage V tile (32 x 64) — no dependence on sMax/sInv
    {
        const float4* vsrc = reinterpret_cast<const float4*>(vBH + (size_t)j0 * DQ);
        float4* vdst = reinterpret_cast<float4*>(vs);
        for (int e = t; e < TILE * DQ / 4; e += 256) vdst[e] = vsrc[e];
    }
    __syncthreads();   // sMax/sInv ready

    // probs: read logit, exp-normalize, write back to attn, stage {p,p}
    for (int e = t; e < NSEL * TILE; e += 256) {
        int s = e >> 5, jj = e & 31;
        size_t a = (size_t)s * LQ + j0 + jj;
        float l = attnBH[a];
        float p = expf(l - sMax[s]) * sInv[s];
        attnBH[a] = p;
        float2 pr = make_float2(p, p);
        pp[e] = *reinterpret_cast<unsigned long long*>(&pr);
    }
    __syncthreads();

    unsigned long long acc[5];
#pragma unroll
    for (int r = 0; r < 5; r++) acc[r] = 0ull;
#pragma unroll 4
    for (int jl = 0; jl < TILE; jl++) {
        unsigned long long vv =
            *reinterpret_cast<const unsigned long long*>(&vs[jl * DQ + 2 * tx]);
#pragma unroll
        for (int r = 0; r < 5; r++) {
            unsigned long long pr = pp[(rg + 8 * r) * TILE + jl];  // bcast LDS.64
            FMA_F32X2(acc[r], pr, vv);
        }
    }
    // store partial: thread owns rows rg+8r, d-pair 2tx (coalesced float2)
    float* part = g_outSelPart + ((size_t)(bh * NJS + js)) * NSEL * DQ;
#pragma unroll
    for (int r = 0; r < 5; r++) {
        int s = rg + 8 * r;
        *reinterpret_cast<float2*>(&part[s * DQ + 2 * tx]) =
            *reinterpret_cast<float2*>(&acc[r]);
    }
}

// ============================================================================
// K5: sum the NJS P@V partials, scatter into out at the selected positions.
// grid (BH, 10): one element per thread, 64-load unrolled chain (high MLP).
// ============================================================================
__global__ void k_scatter(float* __restrict__ out) {
    int bh = blockIdx.x, t = threadIdx.x;
    int e = blockIdx.y * 256 + t;          // 0 .. 2559 (NSEL*DQ = 2560)
    const float* base = g_outSelPart + (size_t)bh * NJS * NSEL * DQ + e;
    float acc = 0.0f;
#pragma unroll
    for (int p = 0; p < NJS; p++) acc += base[(size_t)p * NSEL * DQ];
    int s = e >> 6, d = e & 63;
    out[((size_t)bh * LQ + g_topidx[bh * NSEL + s]) * DQ + d] = acc;
}

// ============================================================================
extern "C" void kernel_launch(void* const* d_in, const int* in_sizes, int n_in,
                              void* d_out, int out_size) {
    const float* q = (const float*)d_in[0];
    const float* k = (const float*)d_in[1];
    const float* v = (const float*)d_in[2];
    const int* ridx = (const int*)d_in[3];

    float* out  = (float*)d_out;                        // [BH, L, D]
    float* attn = out + (size_t)BH * LQ * DQ;           // [BH, NSEL, L]

    // K1: csumA (1024 blocks, first) + measure (16384 blocks)
    k_meas_csumA<<<1024 + (BH * LQ) / 8, 256>>>(q, k, ridx, v);
    // K2: topk (64) + csumB (64)
    k_topk_csumB<<<2 * BH, 256>>>();
    // K3: logits (512 blocks of 256 keys)
    k_logits<<<BH * 8, 256>>>(q, k, attn);
    // K4: csumC (1024, first) + pv (4096 single-tile blocks of 32 keys)
    k_pv_csumC<<<1024 + BH * NJS, 256>>>(v, attn, out);
    // K5: sum partials + scatter (grid BH x 10, elem per thread)
    {
        dim3 grid(BH, 10);
        k_scatter<<<grid, 256>>>(out);
    }
}